// round 13
// baseline (speedup 1.0000x reference)
#include <cuda_runtime.h>
#include <math.h>

// ESN recurrence, GB300 sm_103a — latency-optimized handoff.
//
// Persistent kernel: 128 blocks x 256 threads, 1 CTA/SM.
// Layout: each warp owns 2 full rows; each lane owns 64 k-values arranged so
// the per-step x reads are fully-coalesced LDG.128 from L2 (no smem staging).
// W_res in registers as packed f32x2 pairs (fma.rn.f32x2).
// Grid sync: distributed per-block flags; producer publishes with
// __syncthreads + st.release.gpu (no membar.gl), consumers poll with
// ld.acquire.gpu (4 flags per lane of warp 0), then __syncthreads.
//
// Shapes: input (2048,128) f32, W_in (2048,128) f32, W_res (2048,2048) f32,
// out (2048,2048) f32.  out[t] = erf(U[t] + W_res @ out[t-1]) / sqrt(2048).

#define T_STEPS 2048
#define N_RES   2048
#define D_IN    128
#define G_BLOCKS 128
#define ROWS_PER_BLOCK 16
#define THREADS 256

__device__ unsigned int g_flags[G_BLOCKS];

__global__ void esn_reset_kernel() {
    g_flags[threadIdx.x] = 0u;
}

// ---- Blackwell packed fp32 FMA ----
__device__ __forceinline__ unsigned long long ffma2(unsigned long long a,
                                                    unsigned long long b,
                                                    unsigned long long c) {
    unsigned long long d;
    asm("fma.rn.f32x2 %0, %1, %2, %3;" : "=l"(d) : "l"(a), "l"(b), "l"(c));
    return d;
}
__device__ __forceinline__ unsigned long long pack2(float lo, float hi) {
    unsigned long long p;
    asm("mov.b64 %0, {%1, %2};" : "=l"(p) : "r"(__float_as_uint(lo)), "r"(__float_as_uint(hi)));
    return p;
}
__device__ __forceinline__ float f2_lo(unsigned long long v) {
    return __uint_as_float((unsigned)(v & 0xffffffffull));
}
__device__ __forceinline__ float f2_hi(unsigned long long v) {
    return __uint_as_float((unsigned)(v >> 32));
}
__device__ __forceinline__ unsigned ld_acquire_gpu(const unsigned int* p) {
    unsigned v;
    asm volatile("ld.acquire.gpu.global.u32 %0, [%1];" : "=r"(v) : "l"(p) : "memory");
    return v;
}
__device__ __forceinline__ void st_release_gpu(unsigned int* p, unsigned v) {
    asm volatile("st.release.gpu.global.u32 [%0], %1;" :: "l"(p), "r"(v) : "memory");
}

__global__ void __launch_bounds__(THREADS, 1)
esn_persistent_kernel(const float* __restrict__ input,
                      const float* __restrict__ Win,
                      const float* __restrict__ Wres,
                      float* __restrict__ out)
{
    __shared__ float s_win[ROWS_PER_BLOCK * D_IN];   // 8 KB: W_in slice
    __shared__ float s_in[D_IN];                     // input row t
    __shared__ float s_u[ROWS_PER_BLOCK];            // U[t][rows]

    const int tid  = threadIdx.x;
    const int warp = tid >> 5;     // 0..7; warp owns rows {2w, 2w+1}
    const int lane = tid & 31;
    const int row0 = blockIdx.x * ROWS_PER_BLOCK;

    // ---- one-time: W_in slice to SMEM ----
    for (int i = tid; i < ROWS_PER_BLOCK * D_IN; i += THREADS)
        s_win[i] = Win[row0 * D_IN + i];

    // ---- one-time: W_res -> registers as f32x2 pairs.
    // Lane's k-set: { c*128 + lane*4 + (0..3), c = 0..15 }  (64 k-values).
    // Matches the coalesced per-step x read: x4[c*32 + lane].
    unsigned long long w2[2][32];
    #pragma unroll
    for (int r = 0; r < 2; r++) {
        const float* wrow = Wres + (size_t)(row0 + 2 * warp + r) * N_RES;
        #pragma unroll
        for (int c = 0; c < 16; c++) {
            const double2 wv = *reinterpret_cast<const double2*>(wrow + c * 128 + lane * 4);
            w2[r][2 * c]     = __double_as_longlong(wv.x);
            w2[r][2 * c + 1] = __double_as_longlong(wv.y);
        }
    }
    __syncthreads();

    const float inv_sqrt_n = 0.022097086912079608f;   // 1/sqrt(2048)

    for (int t = 0; t < T_STEPS; t++) {
        // ---- stage input row t (x-independent; overlaps the wait) ----
        if (tid < D_IN / 4) {
            float4 v = __ldcg(reinterpret_cast<const float4*>(input + (size_t)t * D_IN) + tid);
            reinterpret_cast<float4*>(s_in)[tid] = v;
        }
        __syncthreads();

        // ---- U[t][row] = dot(input[t], W_in[row]); 16 threads/row ----
        {
            const int row = tid >> 4;
            const int seg = tid & 15;
            float us = 0.f;
            #pragma unroll
            for (int j = 0; j < 8; j++) {
                const int k = seg * 8 + j;
                us += s_in[k] * s_win[row * D_IN + k];
            }
            #pragma unroll
            for (int off = 8; off; off >>= 1)
                us += __shfl_down_sync(0xffffffffu, us, off, 16);
            if (seg == 0) s_u[row] = us;
        }

        // ---- wait for all producers of x_{t-1}: warp 0, 4 flags per lane,
        //      scalar acquire loads, per-lane exit (no redux, no membar) ----
        if (t > 0 && warp == 0) {
            const unsigned tgt = (unsigned)t;
            unsigned int* f = g_flags + lane * 4;
            while (true) {
                const unsigned a = ld_acquire_gpu(f + 0);
                const unsigned b = ld_acquire_gpu(f + 1);
                const unsigned c = ld_acquire_gpu(f + 2);
                const unsigned d = ld_acquire_gpu(f + 3);
                if (min(min(a, b), min(c, d)) >= tgt) break;
            }
        }
        __syncthreads();   // extends acquire ordering block-wide; also covers s_u

        // ---- main dot: direct coalesced L2 reads, FFMA2 into 2 row-accs ----
        unsigned long long acc0 = 0ull, acc1 = 0ull;
        if (t > 0) {
            const float4* x4 = reinterpret_cast<const float4*>(out + (size_t)(t - 1) * N_RES);
            #pragma unroll
            for (int h = 0; h < 2; h++) {
                float4 xb[8];
                #pragma unroll
                for (int c8 = 0; c8 < 8; c8++)
                    xb[c8] = __ldcg(x4 + (h * 8 + c8) * 32 + lane);
                #pragma unroll
                for (int c8 = 0; c8 < 8; c8++) {
                    const int c = h * 8 + c8;
                    const unsigned long long xa = pack2(xb[c8].x, xb[c8].y);
                    const unsigned long long xv = pack2(xb[c8].z, xb[c8].w);
                    acc0 = ffma2(w2[0][2 * c], xa, acc0);
                    acc0 = ffma2(w2[0][2 * c + 1], xv, acc0);
                    acc1 = ffma2(w2[1][2 * c], xa, acc1);
                    acc1 = ffma2(w2[1][2 * c + 1], xv, acc1);
                }
            }
        }

        // ---- 6-shuffle reduction: row sums land at lane 0 (row 2w) and
        //      lane 16 (row 2w+1) ----
        float a0 = f2_lo(acc0) + f2_hi(acc0);
        float a1 = f2_lo(acc1) + f2_hi(acc1);
        a0 += __shfl_xor_sync(0xffffffffu, a0, 16);
        a1 += __shfl_xor_sync(0xffffffffu, a1, 16);
        float e = (lane & 16) ? a1 : a0;
        e += __shfl_xor_sync(0xffffffffu, e, 8);
        e += __shfl_xor_sync(0xffffffffu, e, 4);
        e += __shfl_xor_sync(0xffffffffu, e, 2);
        e += __shfl_xor_sync(0xffffffffu, e, 1);

        if ((lane & 15) == 0) {
            const int row = 2 * warp + (lane >> 4);
            const float pre = s_u[row] + e;          // t==0: e == 0, pre == U
            out[(size_t)t * N_RES + row0 + row] = erff(pre) * inv_sqrt_n;
        }
        __syncthreads();

        // ---- publish: release-store own flag (CG grid-sync pattern) ----
        if (tid == 0)
            st_release_gpu(&g_flags[blockIdx.x], (unsigned)(t + 1));
    }
}

extern "C" void kernel_launch(void* const* d_in, const int* in_sizes, int n_in,
                              void* d_out, int out_size)
{
    const float* input = (const float*)d_in[0];   // (2048, 128)
    const float* Win   = (const float*)d_in[1];   // (2048, 128)
    const float* Wres  = (const float*)d_in[2];   // (2048, 2048)
    float* out = (float*)d_out;                   // (2048, 2048)

    esn_reset_kernel<<<1, G_BLOCKS>>>();
    esn_persistent_kernel<<<G_BLOCKS, THREADS>>>(input, Win, Wres, out);
}

// round 14
// speedup vs baseline: 3.1317x; 3.1317x over previous
#include <cuda_runtime.h>
#include <math.h>

// ESN recurrence, GB300 sm_103a.
// R14 = R1 body (best: 4520us) with ONLY the grid-sync mechanism replaced:
//   - publish:  __syncthreads + st.release.gpu to per-block flag
//               (replaces __threadfence + single-address atomicAdd)
//   - wait:     warp 0, one ld.acquire.gpu.v4 per lane (4 flags/lane) +
//               __ballot_sync exit, then __syncthreads
// Compute body, smem staging, reduction identical to R1.
//
// Shapes: input (2048,128) f32, W_in (2048,128) f32, W_res (2048,2048) f32,
// out (2048,2048) f32.  out[t] = erf(U[t] + W_res @ out[t-1]) / sqrt(2048).

#define T_STEPS 2048
#define N_RES   2048
#define D_IN    128
#define G_BLOCKS 128
#define ROWS_PER_BLOCK 16
#define THREADS 256

__device__ unsigned int g_flags[G_BLOCKS];

__global__ void esn_reset_kernel() { g_flags[threadIdx.x] = 0u; }

__device__ __forceinline__ void st_release_gpu(unsigned int* p, unsigned v) {
    asm volatile("st.release.gpu.global.u32 [%0], %1;" :: "l"(p), "r"(v) : "memory");
}
__device__ __forceinline__ uint4 ld_acquire_gpu_v4(const unsigned int* p) {
    uint4 v;
    asm volatile("ld.acquire.gpu.global.v4.u32 {%0,%1,%2,%3}, [%4];"
                 : "=r"(v.x), "=r"(v.y), "=r"(v.z), "=r"(v.w) : "l"(p) : "memory");
    return v;
}

__global__ void __launch_bounds__(THREADS, 1)
esn_persistent_kernel(const float* __restrict__ input,
                      const float* __restrict__ Win,
                      const float* __restrict__ Wres,
                      float* __restrict__ out)
{
    __shared__ float4 xs4[N_RES / 4];                    // 8 KB: x_{t-1}
    __shared__ float  s_win[ROWS_PER_BLOCK * D_IN];      // 8 KB: W_in slice
    __shared__ float  s_in[D_IN];                        // input row t
    __shared__ float  s_part[32];                        // 8 warps * 4 rows
    __shared__ float  s_u[ROWS_PER_BLOCK];               // U[t][rows]

    const int tid  = threadIdx.x;
    const int rg   = tid >> 6;     // 0..3  (rowgroup: 4 rows each)
    const int kc   = tid & 63;     // 0..63 (k-chunk of 32)
    const int row0 = blockIdx.x * ROWS_PER_BLOCK;

    // ---- one-time: W_in slice to SMEM ----
    for (int i = tid; i < ROWS_PER_BLOCK * D_IN; i += THREADS)
        s_win[i] = Win[row0 * D_IN + i];

    // ---- one-time: W_res tile into registers, pre-rotated so that the
    //      per-step SMEM x read  xs4[kc*8 + ((q+kc)&7)]  is bank-conflict-free.
    float4 w4[4][8];
    #pragma unroll
    for (int rr = 0; rr < 4; rr++) {
        const float* wrow = Wres + (size_t)(row0 + rg * 4 + rr) * N_RES + kc * 32;
        #pragma unroll
        for (int q = 0; q < 8; q++) {
            const int qe = (q + kc) & 7;
            w4[rr][q] = *reinterpret_cast<const float4*>(wrow + qe * 4);
        }
    }
    __syncthreads();

    const float inv_sqrt_n = 0.022097086912079608f;  // 1/sqrt(2048)
    const int warp = tid >> 5;
    const int lane = tid & 31;

    for (int t = 0; t < T_STEPS; t++) {
        // ---- stage input row t (x-independent: do before the barrier wait) ----
        if (tid < D_IN / 4) {
            float4 v = __ldcg(reinterpret_cast<const float4*>(input + (size_t)t * D_IN) + tid);
            reinterpret_cast<float4*>(s_in)[tid] = v;
        }
        __syncthreads();

        // ---- U[t][row] = dot(input[t], W_in[row]); 16 threads/row, 8 k each ----
        {
            const int row = tid >> 4;
            const int seg = tid & 15;
            float us = 0.f;
            #pragma unroll
            for (int j = 0; j < 8; j++) {
                const int k = seg * 8 + j;
                us += s_in[k] * s_win[row * D_IN + k];
            }
            #pragma unroll
            for (int off = 8; off; off >>= 1)
                us += __shfl_down_sync(0xffffffffu, us, off, 16);
            if (seg == 0) s_u[row] = us;   // SCALE_IN = 1
        }

        // ---- grid wait: warp 0 polls 128 flags, 1 acquire-v4 per lane ----
        if (t > 0) {
            if (warp == 0) {
                const unsigned tgt = (unsigned)t;
                const unsigned int* f = g_flags + lane * 4;
                while (true) {
                    const uint4 v = ld_acquire_gpu_v4(f);
                    const bool done = min(min(v.x, v.y), min(v.z, v.w)) >= tgt;
                    if (__ballot_sync(0xffffffffu, done) == 0xffffffffu) break;
                }
            }
            __syncthreads();   // extends acquire ordering block-wide
            // stage x_{t-1} = out[t-1][:] (L2-only loads)
            const float4* xprev = reinterpret_cast<const float4*>(out + (size_t)(t - 1) * N_RES);
            xs4[tid]           = __ldcg(xprev + tid);
            xs4[tid + THREADS] = __ldcg(xprev + tid + THREADS);
        }
        __syncthreads();

        // ---- main dot: acc[rr] = sum_k W[row][k] * x[k] over this thread's 32 k ----
        float acc0 = 0.f, acc1 = 0.f, acc2 = 0.f, acc3 = 0.f;
        if (t > 0) {
            const int base = kc * 8;
            #pragma unroll
            for (int q = 0; q < 8; q++) {
                const float4 xv = xs4[base + ((q + kc) & 7)];
                acc0 = fmaf(w4[0][q].x, xv.x, acc0);
                acc0 = fmaf(w4[0][q].y, xv.y, acc0);
                acc0 = fmaf(w4[0][q].z, xv.z, acc0);
                acc0 = fmaf(w4[0][q].w, xv.w, acc0);
                acc1 = fmaf(w4[1][q].x, xv.x, acc1);
                acc1 = fmaf(w4[1][q].y, xv.y, acc1);
                acc1 = fmaf(w4[1][q].z, xv.z, acc1);
                acc1 = fmaf(w4[1][q].w, xv.w, acc1);
                acc2 = fmaf(w4[2][q].x, xv.x, acc2);
                acc2 = fmaf(w4[2][q].y, xv.y, acc2);
                acc2 = fmaf(w4[2][q].z, xv.z, acc2);
                acc2 = fmaf(w4[2][q].w, xv.w, acc2);
                acc3 = fmaf(w4[3][q].x, xv.x, acc3);
                acc3 = fmaf(w4[3][q].y, xv.y, acc3);
                acc3 = fmaf(w4[3][q].z, xv.z, acc3);
                acc3 = fmaf(w4[3][q].w, xv.w, acc3);
            }
        }

        // ---- reduce across 32 lanes ----
        #pragma unroll
        for (int off = 16; off; off >>= 1) {
            acc0 += __shfl_xor_sync(0xffffffffu, acc0, off);
            acc1 += __shfl_xor_sync(0xffffffffu, acc1, off);
            acc2 += __shfl_xor_sync(0xffffffffu, acc2, off);
            acc3 += __shfl_xor_sync(0xffffffffu, acc3, off);
        }
        if (lane == 0) {
            s_part[warp * 4 + 0] = acc0;
            s_part[warp * 4 + 1] = acc1;
            s_part[warp * 4 + 2] = acc2;
            s_part[warp * 4 + 3] = acc3;
        }
        __syncthreads();

        // ---- finalize 16 rows: combine warp-halves, add U, erf, store ----
        if (tid < ROWS_PER_BLOCK) {
            const int rg2 = tid >> 2;
            const int rr  = tid & 3;
            const float sum = s_part[(rg2 * 2 + 0) * 4 + rr] +
                              s_part[(rg2 * 2 + 1) * 4 + rr];
            const float pre = s_u[tid] + sum;
            out[(size_t)t * N_RES + row0 + tid] = erff(pre) * inv_sqrt_n;
        }
        __syncthreads();

        // ---- publish: release-store own flag (CG grid-sync pattern) ----
        if (tid == 0)
            st_release_gpu(&g_flags[blockIdx.x], (unsigned)(t + 1));
    }
}

extern "C" void kernel_launch(void* const* d_in, const int* in_sizes, int n_in,
                              void* d_out, int out_size)
{
    const float* input = (const float*)d_in[0];   // (2048, 128)
    const float* Win   = (const float*)d_in[1];   // (2048, 128)
    const float* Wres  = (const float*)d_in[2];   // (2048, 2048)
    float* out = (float*)d_out;                   // (2048, 2048)

    esn_reset_kernel<<<1, G_BLOCKS>>>();
    esn_persistent_kernel<<<G_BLOCKS, THREADS>>>(input, Win, Wres, out);
}